// round 1
// baseline (speedup 1.0000x reference)
#include <cuda_runtime.h>

#define N_NODES 40000
#define N_EDGES 640000
#define EMBED   128
#define NTYPE   64

// ---------------- scratch (static device globals; no allocs allowed) ----------------
__device__ float g_h[N_NODES * EMBED];       // node features
__device__ float g_t[N_NODES * EMBED];       // post-GEMM features (reused at width 64 for decoder)
__device__ int   g_counts[N_NODES];
__device__ int   g_rowptr[N_NODES + 1];
__device__ int   g_cursor[N_NODES];
__device__ float g_dinv[N_NODES];
__device__ float g_selfw[N_NODES];           // dinv^2 (self-loop norm)
__device__ int2  g_edges[N_EDGES];           // {src, norm_bits} sorted-by-dst via CSR fill
__device__ int   g_x64;                      // 1 if x is int64, else int32
__device__ int   g_e64;                      // 1 if edge_index is int64

// ---------------- helpers ----------------
__device__ __forceinline__ int load_idx(const void* p, long long i, int is64) {
    return is64 ? (int)((const long long*)p)[i] : ((const int*)p)[i];
}

__device__ __forceinline__ unsigned long long pk2(float x) {
    unsigned long long r;
    unsigned int b = __float_as_uint(x);
    asm("mov.b64 %0, {%1, %1};" : "=l"(r) : "r"(b));
    return r;
}

__device__ __forceinline__ unsigned long long ffma2(unsigned long long a,
                                                    unsigned long long b,
                                                    unsigned long long c) {
    asm("fma.rn.f32x2 %0, %1, %2, %0;" : "+l"(c) : "l"(a), "l"(b));
    return c;
}

// ---------------- dtype detection (int64 vs int32) ----------------
__global__ void k_detect(const void* xp, const void* ep) {
    if (threadIdx.x == 0 && blockIdx.x == 0) {
        const unsigned int* w = (const unsigned int*)xp;
        int is64 = 1;
        for (int i = 0; i < 64; i++)
            if (w[2 * i + 1] != 0u) { is64 = 0; break; }
        g_x64 = is64;
        const unsigned int* we = (const unsigned int*)ep;
        int e64 = 1;
        for (int i = 0; i < 64; i++)
            if (we[2 * i + 1] != 0u) { e64 = 0; break; }
        g_e64 = e64;
    }
}

// ---------------- CSR build ----------------
__global__ void k_zero() {
    int i = blockIdx.x * blockDim.x + threadIdx.x;
    if (i < N_NODES) g_counts[i] = 0;
}

__global__ void k_count(const void* ei) {
    int e = blockIdx.x * blockDim.x + threadIdx.x;
    if (e < N_EDGES) {
        int d = load_idx(ei, (long long)N_EDGES + e, g_e64);
        atomicAdd(&g_counts[d], 1);
    }
}

__global__ void k_dinv() {
    int v = blockIdx.x * blockDim.x + threadIdx.x;
    if (v < N_NODES) {
        float deg = (float)(g_counts[v] + 1);   // +1 self loop (dst side)
        float dv = rsqrtf(deg);
        g_dinv[v] = dv;
        g_selfw[v] = dv * dv;
    }
}

__global__ void k_scan() {   // single block, 1024 threads
    __shared__ int partial[1024];
    const int CH = (N_NODES + 1023) / 1024;   // 40
    int t = threadIdx.x;
    int base = t * CH;
    int s = 0;
    for (int i = 0; i < CH; i++)
        if (base + i < N_NODES) s += g_counts[base + i];
    partial[t] = s;
    __syncthreads();
    for (int off = 1; off < 1024; off <<= 1) {
        int x = (t >= off) ? partial[t - off] : 0;
        __syncthreads();
        partial[t] += x;
        __syncthreads();
    }
    int run = partial[t] - s;   // exclusive prefix of this chunk
    for (int i = 0; i < CH; i++) {
        int idx = base + i;
        if (idx < N_NODES) {
            g_rowptr[idx] = run;
            g_cursor[idx] = run;
            run += g_counts[idx];
        }
    }
    if (t == 1023) g_rowptr[N_NODES] = run;
}

__global__ void k_fill(const void* ei) {
    int e = blockIdx.x * blockDim.x + threadIdx.x;
    if (e < N_EDGES) {
        int is64 = g_e64;
        int s = load_idx(ei, e, is64);
        int d = load_idx(ei, (long long)N_EDGES + e, is64);
        int pos = atomicAdd(&g_cursor[d], 1);
        int2 v;
        v.x = s;
        v.y = __float_as_int(g_dinv[s] * g_dinv[d]);
        g_edges[pos] = v;
    }
}

// ---------------- embedding gather: h = W_in[x] ----------------
__global__ void k_embed(const void* xp, const float* __restrict__ Win) {
    int id = blockIdx.x * blockDim.x + threadIdx.x;
    if (id < N_NODES * 32) {
        int v = id >> 5;
        int c4 = id & 31;
        int row = load_idx(xp, v, g_x64);
        *(float4*)(g_h + (long)v * EMBED + c4 * 4) =
            *(const float4*)(Win + (long)row * EMBED + c4 * 4);
    }
}

// ---------------- GEMM: C[M][NCOL] = A[M][128] @ W[128][NCOL], f32x2 packed FMA --------
template <int NCOL>
__device__ __forceinline__ void gemm_body(const float* __restrict__ A,
                                          const float* __restrict__ W,
                                          float* __restrict__ C) {
    constexpr int CG = NCOL / 8;     // column groups (8 cols per thread)
    constexpr int RG = 256 / CG;     // row groups (4 rows per thread)
    constexpr int MT = RG * 4;       // rows per block
    extern __shared__ float smem[];
    float* As = smem;                 // [MT][128]
    float* Ws = smem + MT * EMBED;    // [128][NCOL]
    int tid = threadIdx.x;
    int row0 = blockIdx.x * MT;

    // stage A tile (coalesced, zero-padded past M)
    for (int i = tid; i < MT * (EMBED / 4); i += 256) {
        int r = i >> 5;           // EMBED/4 == 32
        int c4 = i & 31;
        int gr = row0 + r;
        float4 v = make_float4(0.f, 0.f, 0.f, 0.f);
        if (gr < N_NODES) v = *(const float4*)(A + (long)gr * EMBED + c4 * 4);
        *(float4*)(As + r * EMBED + c4 * 4) = v;
    }
    // stage W
    for (int i = tid; i < EMBED * NCOL / 4; i += 256)
        *(float4*)(Ws + i * 4) = *(const float4*)(W + i * 4);
    __syncthreads();

    int cg = tid % CG;
    int rg = tid / CG;
    int c0 = cg * 8;

    unsigned long long acc[4][4];
    #pragma unroll
    for (int i = 0; i < 4; i++)
        #pragma unroll
        for (int p = 0; p < 4; p++) acc[i][p] = 0ULL;

    #pragma unroll 2
    for (int k = 0; k < EMBED; k += 4) {
        float4 a[4];
        #pragma unroll
        for (int i = 0; i < 4; i++)
            a[i] = *(const float4*)(As + (rg * 4 + i) * EMBED + k);
        #pragma unroll
        for (int ks = 0; ks < 4; ks++) {
            const float* wr = Ws + (k + ks) * NCOL + c0;
            ulonglong2 w01 = *(const ulonglong2*)wr;
            ulonglong2 w23 = *(const ulonglong2*)(wr + 4);
            #pragma unroll
            for (int i = 0; i < 4; i++) {
                float av = ((const float*)&a[i])[ks];
                unsigned long long a2 = pk2(av);
                acc[i][0] = ffma2(a2, w01.x, acc[i][0]);
                acc[i][1] = ffma2(a2, w01.y, acc[i][1]);
                acc[i][2] = ffma2(a2, w23.x, acc[i][2]);
                acc[i][3] = ffma2(a2, w23.y, acc[i][3]);
            }
        }
    }

    #pragma unroll
    for (int i = 0; i < 4; i++) {
        int gr = row0 + rg * 4 + i;
        if (gr < N_NODES) {
            ulonglong2 s0, s1;
            s0.x = acc[i][0]; s0.y = acc[i][1];
            s1.x = acc[i][2]; s1.y = acc[i][3];
            *(ulonglong2*)(C + (long)gr * NCOL + c0)     = s0;
            *(ulonglong2*)(C + (long)gr * NCOL + c0 + 4) = s1;
        }
    }
}

__global__ void __launch_bounds__(256, 2) k_gemm_conv(const float* __restrict__ W) {
    gemm_body<128>(g_h, W, g_t);
}
__global__ void __launch_bounds__(256, 2) k_gemm_dec(const float* __restrict__ W) {
    gemm_body<64>(g_h, W, g_t);
}

// ---------------- aggregation: out[v] = [relu](selfw*t[v] + sum_in norm*t[u] + b) ------
template <int VEC, bool RELU>
__device__ __forceinline__ void agg_body(const float* __restrict__ T,
                                         const float* __restrict__ bias,
                                         float* __restrict__ out) {
    constexpr int W = VEC * 32;
    int v = blockIdx.x * 8 + (threadIdx.x >> 5);
    int lane = threadIdx.x & 31;

    const float* trow = T + (long)v * W + lane * VEC;
    float acc[VEC];
    float sw = g_selfw[v];
    if (VEC == 4) {
        float4 t0 = *(const float4*)trow;
        acc[0] = sw * t0.x; acc[1] = sw * t0.y; acc[2] = sw * t0.z; acc[3] = sw * t0.w;
    } else {
        float2 t0 = *(const float2*)trow;
        acc[0] = sw * t0.x; acc[1] = sw * t0.y;
    }

    int jb = g_rowptr[v], je = g_rowptr[v + 1];
    int j = jb;
    for (; j + 1 < je; j += 2) {
        int2 e0 = g_edges[j];
        int2 e1 = g_edges[j + 1];
        const float* r0 = T + (long)e0.x * W + lane * VEC;
        const float* r1 = T + (long)e1.x * W + lane * VEC;
        float w0 = __int_as_float(e0.y);
        float w1 = __int_as_float(e1.y);
        if (VEC == 4) {
            float4 t0 = *(const float4*)r0;
            float4 t1 = *(const float4*)r1;
            acc[0] = fmaf(w0, t0.x, acc[0]); acc[1] = fmaf(w0, t0.y, acc[1]);
            acc[2] = fmaf(w0, t0.z, acc[2]); acc[3] = fmaf(w0, t0.w, acc[3]);
            acc[0] = fmaf(w1, t1.x, acc[0]); acc[1] = fmaf(w1, t1.y, acc[1]);
            acc[2] = fmaf(w1, t1.z, acc[2]); acc[3] = fmaf(w1, t1.w, acc[3]);
        } else {
            float2 t0 = *(const float2*)r0;
            float2 t1 = *(const float2*)r1;
            acc[0] = fmaf(w0, t0.x, acc[0]); acc[1] = fmaf(w0, t0.y, acc[1]);
            acc[0] = fmaf(w1, t1.x, acc[0]); acc[1] = fmaf(w1, t1.y, acc[1]);
        }
    }
    if (j < je) {
        int2 e0 = g_edges[j];
        const float* r0 = T + (long)e0.x * W + lane * VEC;
        float w0 = __int_as_float(e0.y);
        if (VEC == 4) {
            float4 t0 = *(const float4*)r0;
            acc[0] = fmaf(w0, t0.x, acc[0]); acc[1] = fmaf(w0, t0.y, acc[1]);
            acc[2] = fmaf(w0, t0.z, acc[2]); acc[3] = fmaf(w0, t0.w, acc[3]);
        } else {
            float2 t0 = *(const float2*)r0;
            acc[0] = fmaf(w0, t0.x, acc[0]); acc[1] = fmaf(w0, t0.y, acc[1]);
        }
    }

    #pragma unroll
    for (int i = 0; i < VEC; i++) {
        acc[i] += bias[lane * VEC + i];
        if (RELU) acc[i] = fmaxf(acc[i], 0.f);
    }
    float* orow = out + (long)v * W + lane * VEC;
    if (VEC == 4) {
        float4 o; o.x = acc[0]; o.y = acc[1]; o.z = acc[2]; o.w = acc[3];
        *(float4*)orow = o;
    } else {
        float2 o; o.x = acc[0]; o.y = acc[1];
        *(float2*)orow = o;
    }
}

__global__ void __launch_bounds__(256) k_agg_conv(const float* __restrict__ bias) {
    agg_body<4, true>(g_t, bias, g_h);
}
__global__ void __launch_bounds__(256) k_agg_dec(const float* __restrict__ bias,
                                                 float* __restrict__ out) {
    agg_body<2, false>(g_t, bias, out);
}

// ---------------- launch ----------------
extern "C" void kernel_launch(void* const* d_in, const int* in_sizes, int n_in,
                              void* d_out, int out_size) {
    const void*  x      = d_in[0];
    const void*  ei     = d_in[1];
    const float* W_in   = (const float*)d_in[2];
    const float* W_conv = (const float*)d_in[3];
    const float* b_conv = (const float*)d_in[4];
    const float* W_dec  = (const float*)d_in[5];
    const float* b_dec  = (const float*)d_in[6];
    float* out = (float*)d_out;

    cudaFuncSetAttribute(k_gemm_conv, cudaFuncAttributeMaxDynamicSharedMemorySize, 98304);
    cudaFuncSetAttribute(k_gemm_dec,  cudaFuncAttributeMaxDynamicSharedMemorySize, 98304);

    k_detect<<<1, 32>>>(x, ei);
    k_zero<<<(N_NODES + 255) / 256, 256>>>();
    k_count<<<(N_EDGES + 255) / 256, 256>>>(ei);
    k_dinv<<<(N_NODES + 255) / 256, 256>>>();
    k_scan<<<1, 1024>>>();
    k_fill<<<(N_EDGES + 255) / 256, 256>>>(ei);
    k_embed<<<(N_NODES * 32) / 256, 256>>>(x, W_in);

    for (int it = 0; it < 4; it++) {
        k_gemm_conv<<<625, 256, 98304>>>(W_conv);
        k_agg_conv<<<5000, 256>>>(b_conv);
    }
    k_gemm_dec<<<313, 256, 98304>>>(W_dec);
    k_agg_dec<<<5000, 256>>>(b_dec, out);
}

// round 4
// speedup vs baseline: 1.3870x; 1.3870x over previous
#include <cuda_runtime.h>
#include <cuda_bf16.h>

#define N_NODES 40000
#define N_EDGES 640000
#define EMBED   128
#define NTYPE   64

// ---------------- scratch (static device globals; no allocs allowed) ----------------
__device__ float          g_t[N_NODES * EMBED];
__device__ unsigned short g_hb[N_NODES * EMBED];   // bf16 bits, high part
__device__ unsigned short g_hl[N_NODES * EMBED];   // bf16 bits, low part
__device__ int   g_counts[N_NODES];
__device__ int   g_rowptr[N_NODES + 1];
__device__ int   g_cursor[N_NODES];
__device__ float g_dinv[N_NODES];
__device__ float g_selfw[N_NODES];
__device__ int2  g_edges[N_EDGES];
__device__ int   g_x64;
__device__ int   g_e64;
// weights as bf16 hi/lo, layout [n][k] (k contiguous) = col-major K x N for mma B
__device__ unsigned short g_Wch[128 * 128];
__device__ unsigned short g_Wcl[128 * 128];
__device__ unsigned short g_Wdh[64 * 128];
__device__ unsigned short g_Wdl[64 * 128];

// ---------------- helpers ----------------
__device__ __forceinline__ int load_idx(const void* p, long long i, int is64) {
    if (is64) return (int)((const long long*)p)[i];
    return ((const int*)p)[i];
}

__device__ __forceinline__ unsigned short f2bf(float x) {
    return __bfloat16_as_ushort(__float2bfloat16_rn(x));
}
__device__ __forceinline__ float bf2f(unsigned short u) {
    return __bfloat162float(__ushort_as_bfloat16(u));
}

__device__ __forceinline__ unsigned int smem_u32(const void* p) {
    unsigned int a;
    asm("{ .reg .u64 t; cvta.to.shared.u64 t, %1; cvt.u32.u64 %0, t; }" : "=r"(a) : "l"(p));
    return a;
}

__device__ __forceinline__ void ldsm_x4(unsigned int& r0, unsigned int& r1,
                                        unsigned int& r2, unsigned int& r3,
                                        unsigned int addr) {
    asm volatile("ldmatrix.sync.aligned.m8n8.x4.shared.b16 {%0,%1,%2,%3}, [%4];"
                 : "=r"(r0), "=r"(r1), "=r"(r2), "=r"(r3) : "r"(addr));
}

__device__ __forceinline__ void ldsm_x2(unsigned int& r0, unsigned int& r1,
                                        unsigned int addr) {
    asm volatile("ldmatrix.sync.aligned.m8n8.x2.shared.b16 {%0,%1}, [%2];"
                 : "=r"(r0), "=r"(r1) : "r"(addr));
}

__device__ __forceinline__ void mma_bf16(float* d, unsigned int a0, unsigned int a1,
                                         unsigned int a2, unsigned int a3,
                                         unsigned int b0, unsigned int b1) {
    asm volatile(
        "mma.sync.aligned.m16n8k16.row.col.f32.bf16.bf16.f32 "
        "{%0,%1,%2,%3}, {%4,%5,%6,%7}, {%8,%9}, {%0,%1,%2,%3};"
        : "+f"(d[0]), "+f"(d[1]), "+f"(d[2]), "+f"(d[3])
        : "r"(a0), "r"(a1), "r"(a2), "r"(a3), "r"(b0), "r"(b1));
}

// ---------------- dtype detection ----------------
__global__ void k_detect(const void* xp, const void* ep) {
    if (threadIdx.x == 0 && blockIdx.x == 0) {
        const unsigned int* w = (const unsigned int*)xp;
        int is64 = 1;
        for (int i = 0; i < 64; i++) {
            if (w[2 * i + 1] != 0u) { is64 = 0; break; }
        }
        g_x64 = is64;
        const unsigned int* we = (const unsigned int*)ep;
        int e64 = 1;
        for (int i = 0; i < 64; i++) {
            if (we[2 * i + 1] != 0u) { e64 = 0; break; }
        }
        g_e64 = e64;
    }
}

// ---------------- CSR build ----------------
__global__ void k_zero() {
    int i = blockIdx.x * blockDim.x + threadIdx.x;
    if (i < N_NODES) g_counts[i] = 0;
}

__global__ void k_count(const void* ei) {
    int e = blockIdx.x * blockDim.x + threadIdx.x;
    if (e < N_EDGES) {
        int d = load_idx(ei, (long long)N_EDGES + e, g_e64);
        atomicAdd(&g_counts[d], 1);
    }
}

__global__ void k_dinv() {
    int v = blockIdx.x * blockDim.x + threadIdx.x;
    if (v < N_NODES) {
        float deg = (float)(g_counts[v] + 1);
        float dv = rsqrtf(deg);
        g_dinv[v] = dv;
        g_selfw[v] = dv * dv;
    }
}

__global__ void k_scan() {
    __shared__ int partial[1024];
    const int CH = (N_NODES + 1023) / 1024;
    int t = threadIdx.x;
    int base = t * CH;
    int s = 0;
    for (int i = 0; i < CH; i++) {
        if (base + i < N_NODES) s += g_counts[base + i];
    }
    partial[t] = s;
    __syncthreads();
    for (int off = 1; off < 1024; off <<= 1) {
        int xv = (t >= off) ? partial[t - off] : 0;
        __syncthreads();
        partial[t] += xv;
        __syncthreads();
    }
    int run = partial[t] - s;
    for (int i = 0; i < CH; i++) {
        int idx = base + i;
        if (idx < N_NODES) {
            g_rowptr[idx] = run;
            g_cursor[idx] = run;
            run += g_counts[idx];
        }
    }
    if (t == 1023) g_rowptr[N_NODES] = run;
}

__global__ void k_fill(const void* ei) {
    int e = blockIdx.x * blockDim.x + threadIdx.x;
    if (e < N_EDGES) {
        int is64 = g_e64;
        int s = load_idx(ei, e, is64);
        int d = load_idx(ei, (long long)N_EDGES + e, is64);
        int pos = atomicAdd(&g_cursor[d], 1);
        int2 v;
        v.x = s;
        v.y = __float_as_int(g_dinv[s] * g_dinv[d]);
        g_edges[pos] = v;
    }
}

// ---------------- weight prep: bf16 hi/lo, [n][k] layout ----------------
__global__ void k_prepW(const float* __restrict__ Wc, const float* __restrict__ Wd) {
    int i = blockIdx.x * blockDim.x + threadIdx.x;
    if (i < 16384) {
        int n = i >> 7;
        int k = i & 127;
        float v = Wc[k * 128 + n];
        unsigned short h = f2bf(v);
        unsigned short l = f2bf(v - bf2f(h));
        g_Wch[n * 128 + k] = h;
        g_Wcl[n * 128 + k] = l;
    } else if (i < 24576) {
        int j = i - 16384;
        int n = j >> 7;
        int k = j & 127;
        float v = Wd[k * 64 + n];
        unsigned short h = f2bf(v);
        unsigned short l = f2bf(v - bf2f(h));
        g_Wdh[n * 128 + k] = h;
        g_Wdl[n * 128 + k] = l;
    }
}

// ---------------- embedding gather ----------------
__global__ void k_embed(const void* xp, const float* __restrict__ Win) {
    int id = blockIdx.x * blockDim.x + threadIdx.x;
    if (id < N_NODES * 16) {
        int v = id >> 4;
        int k0 = (id & 15) * 8;
        int row = load_idx(xp, v, g_x64);
        const float* src = Win + (long)row * EMBED + k0;
        unsigned short hb[8];
        unsigned short lb[8];
        #pragma unroll
        for (int q = 0; q < 8; q++) {
            float a = src[q];
            unsigned short h = f2bf(a);
            hb[q] = h;
            lb[q] = f2bf(a - bf2f(h));
        }
        *(uint4*)(g_hb + (long)v * EMBED + k0) = *(uint4*)hb;
        *(uint4*)(g_hl + (long)v * EMBED + k0) = *(uint4*)lb;
    }
}

// ---------------- tensor-core GEMM (mma.sync bf16, split hi/lo, 3 passes) ----------
// C[M][NCOL] = (Ah+Al) @ (Wh+Wl)^T-ish : passes Ah*Wh + Ah*Wl + Al*Wh, fp32 acc.
// A rows in g_hb/g_hl [row][k]; W in g_W*[n][k].
template <int NCOL>
__device__ __forceinline__ void mma_gemm_body(const unsigned short* __restrict__ Wh,
                                              const unsigned short* __restrict__ Wl,
                                              float* __restrict__ C) {
    const int PAD = 136;                 // halfs per smem row (bank rotate)
    const int NT = NCOL / 8;             // n-tiles per warp
    extern __shared__ unsigned short sm[];
    unsigned short* Ah = sm;                       // [128][PAD]
    unsigned short* Al = Ah + 128 * PAD;
    unsigned short* Bh = Al + 128 * PAD;           // [NCOL][PAD]
    unsigned short* Bl = Bh + NCOL * PAD;

    int tid = threadIdx.x;
    int wid = tid >> 5;
    int lane = tid & 31;
    int row0 = blockIdx.x * 128;

    // stage A hi/lo (128 rows x 128 halfs, 8-half chunks)
    for (int i = tid; i < 2048; i += 256) {
        int r = i >> 4;
        int k0 = (i & 15) * 8;
        int gr = row0 + r;
        uint4 vh = make_uint4(0u, 0u, 0u, 0u);
        uint4 vl = make_uint4(0u, 0u, 0u, 0u);
        if (gr < N_NODES) {
            vh = *(const uint4*)(g_hb + (long)gr * EMBED + k0);
            vl = *(const uint4*)(g_hl + (long)gr * EMBED + k0);
        }
        *(uint4*)(Ah + r * PAD + k0) = vh;
        *(uint4*)(Al + r * PAD + k0) = vl;
    }
    // stage W hi/lo (NCOL rows x 128 halfs)
    for (int i = tid; i < NCOL * 16; i += 256) {
        int r = i >> 4;
        int k0 = (i & 15) * 8;
        *(uint4*)(Bh + r * PAD + k0) = *(const uint4*)(Wh + r * 128 + k0);
        *(uint4*)(Bl + r * PAD + k0) = *(const uint4*)(Wl + r * 128 + k0);
    }
    __syncthreads();

    int m0 = wid * 16;
    float acc[NT][4];
    #pragma unroll
    for (int j = 0; j < NT; j++) {
        #pragma unroll
        for (int q = 0; q < 4; q++) acc[j][q] = 0.0f;
    }

    const unsigned int sb = smem_u32(sm);
    // ldmatrix lane address offsets (halfs)
    unsigned int a_off = (unsigned int)((m0 + (lane & 15)) * PAD + (lane >> 4) * 8) * 2u;
    unsigned int b_off = (unsigned int)(((lane & 15) & 7) * PAD + ((lane & 15) >> 3) * 8) * 2u;
    unsigned int a_h = sb + a_off;                              // into Ah
    unsigned int a_l = sb + (unsigned int)(128 * PAD * 2) + a_off;  // into Al
    unsigned int b_h = sb + (unsigned int)(256 * PAD * 2) + b_off;  // into Bh
    unsigned int b_l = b_h + (unsigned int)(NCOL * PAD * 2);        // into Bl

    #pragma unroll 1
    for (int pass = 0; pass < 3; pass++) {
        unsigned int abase = (pass == 2) ? a_l : a_h;
        unsigned int bbase = (pass == 1) ? b_l : b_h;
        #pragma unroll
        for (int ks = 0; ks < 8; ks++) {
            unsigned int a0, a1, a2, a3;
            ldsm_x4(a0, a1, a2, a3, abase + (unsigned int)(ks * 32));
            #pragma unroll
            for (int j = 0; j < NT; j++) {
                unsigned int b0, b1;
                ldsm_x2(b0, b1, bbase + (unsigned int)(j * 8 * PAD * 2 + ks * 32));
                mma_bf16(acc[j], a0, a1, a2, a3, b0, b1);
            }
        }
    }

    // epilogue: d0,d1 -> (m0+lane/4, n0+(lane%4)*2) ; d2,d3 -> row+8
    int mrow = m0 + (lane >> 2);
    int nc0 = (lane & 3) * 2;
    int gr0 = row0 + mrow;
    int gr1 = gr0 + 8;
    #pragma unroll
    for (int j = 0; j < NT; j++) {
        if (gr0 < N_NODES) {
            float2 v;
            v.x = acc[j][0];
            v.y = acc[j][1];
            *(float2*)(C + (long)gr0 * NCOL + j * 8 + nc0) = v;
        }
        if (gr1 < N_NODES) {
            float2 v;
            v.x = acc[j][2];
            v.y = acc[j][3];
            *(float2*)(C + (long)gr1 * NCOL + j * 8 + nc0) = v;
        }
    }
}

__global__ void __launch_bounds__(256, 1) k_mm_conv() {
    mma_gemm_body<128>(g_Wch, g_Wcl, g_t);
}
__global__ void __launch_bounds__(256, 1) k_mm_dec() {
    mma_gemm_body<64>(g_Wdh, g_Wdl, g_t);
}

// ---------------- aggregation ----------------
// out[v] = postproc( selfw[v]*t[v] + sum_{(u->v)} norm*t[u] + bias )
template <int VEC, bool RELU>
__device__ __forceinline__ void agg_body(const float* __restrict__ T,
                                         const float* __restrict__ bias,
                                         float* __restrict__ outF) {
    const int WIDTH = VEC * 32;
    int v = blockIdx.x * 8 + (threadIdx.x >> 5);
    int lane = threadIdx.x & 31;

    const float* trow = T + (long)v * WIDTH + lane * VEC;
    float acc[VEC];
    float sw = g_selfw[v];
    #pragma unroll
    for (int i = 0; i < VEC; i++) {
        acc[i] = sw * trow[i];
    }

    int jb = g_rowptr[v];
    int je = g_rowptr[v + 1];
    int j = jb;
    for (; j + 1 < je; j += 2) {
        int2 e0 = g_edges[j];
        int2 e1 = g_edges[j + 1];
        const float* r0 = T + (long)e0.x * WIDTH + lane * VEC;
        const float* r1 = T + (long)e1.x * WIDTH + lane * VEC;
        float w0 = __int_as_float(e0.y);
        float w1 = __int_as_float(e1.y);
        float t0[VEC];
        float t1[VEC];
        if (VEC == 4) {
            *(float4*)t0 = *(const float4*)r0;
            *(float4*)t1 = *(const float4*)r1;
        } else {
            *(float2*)t0 = *(const float2*)r0;
            *(float2*)t1 = *(const float2*)r1;
        }
        #pragma unroll
        for (int i = 0; i < VEC; i++) {
            acc[i] = fmaf(w0, t0[i], acc[i]);
        }
        #pragma unroll
        for (int i = 0; i < VEC; i++) {
            acc[i] = fmaf(w1, t1[i], acc[i]);
        }
    }
    if (j < je) {
        int2 e0 = g_edges[j];
        const float* r0 = T + (long)e0.x * WIDTH + lane * VEC;
        float w0 = __int_as_float(e0.y);
        float t0[VEC];
        if (VEC == 4) {
            *(float4*)t0 = *(const float4*)r0;
        } else {
            *(float2*)t0 = *(const float2*)r0;
        }
        #pragma unroll
        for (int i = 0; i < VEC; i++) {
            acc[i] = fmaf(w0, t0[i], acc[i]);
        }
    }

    if (RELU) {
        unsigned short hb[VEC];
        unsigned short lb[VEC];
        #pragma unroll
        for (int i = 0; i < VEC; i++) {
            float a = fmaxf(acc[i] + bias[lane * VEC + i], 0.0f);
            unsigned short h = f2bf(a);
            hb[i] = h;
            lb[i] = f2bf(a - bf2f(h));
        }
        *(uint2*)(g_hb + (long)v * WIDTH + lane * VEC) = *(uint2*)hb;
        *(uint2*)(g_hl + (long)v * WIDTH + lane * VEC) = *(uint2*)lb;
    } else {
        float o[VEC];
        #pragma unroll
        for (int i = 0; i < VEC; i++) {
            o[i] = acc[i] + bias[lane * VEC + i];
        }
        float* orow = outF + (long)v * WIDTH + lane * VEC;
        if (VEC == 4) {
            *(float4*)orow = *(float4*)o;
        } else {
            *(float2*)orow = *(float2*)o;
        }
    }
}

__global__ void __launch_bounds__(256) k_agg_conv(const float* __restrict__ bias) {
    agg_body<4, true>(g_t, bias, (float*)0);
}
__global__ void __launch_bounds__(256) k_agg_dec(const float* __restrict__ bias,
                                                 float* __restrict__ out) {
    agg_body<2, false>(g_t, bias, out);
}

// ---------------- launch ----------------
extern "C" void kernel_launch(void* const* d_in, const int* in_sizes, int n_in,
                              void* d_out, int out_size) {
    const void*  x      = d_in[0];
    const void*  ei     = d_in[1];
    const float* W_in   = (const float*)d_in[2];
    const float* W_conv = (const float*)d_in[3];
    const float* b_conv = (const float*)d_in[4];
    const float* W_dec  = (const float*)d_in[5];
    const float* b_dec  = (const float*)d_in[6];
    float* out = (float*)d_out;

    const int PAD = 136;
    const int SMEM_CONV = (2 * 128 + 2 * 128) * PAD * 2;  // 139264
    const int SMEM_DEC  = (2 * 128 + 2 * 64) * PAD * 2;   // 104448
    cudaFuncSetAttribute(k_mm_conv, cudaFuncAttributeMaxDynamicSharedMemorySize, SMEM_CONV);
    cudaFuncSetAttribute(k_mm_dec,  cudaFuncAttributeMaxDynamicSharedMemorySize, SMEM_DEC);

    k_detect<<<1, 32>>>(x, ei);
    k_zero<<<(N_NODES + 255) / 256, 256>>>();
    k_count<<<(N_EDGES + 255) / 256, 256>>>(ei);
    k_dinv<<<(N_NODES + 255) / 256, 256>>>();
    k_scan<<<1, 1024>>>();
    k_fill<<<(N_EDGES + 255) / 256, 256>>>(ei);
    k_prepW<<<96, 256>>>(W_conv, W_dec);
    k_embed<<<(N_NODES * 16 + 255) / 256, 256>>>(x, W_in);

    const int GEMM_BLOCKS = (N_NODES + 127) / 128;   // 313
    for (int it = 0; it < 4; it++) {
        k_mm_conv<<<GEMM_BLOCKS, 256, SMEM_CONV>>>();
        k_agg_conv<<<5000, 256>>>(b_conv);
    }
    k_mm_dec<<<GEMM_BLOCKS, 256, SMEM_DEC>>>();
    k_agg_dec<<<5000, 256>>>(b_dec, out);
}

// round 5
// speedup vs baseline: 1.4995x; 1.0811x over previous
#include <cuda_runtime.h>
#include <cuda_bf16.h>
#include <cuda_fp16.h>

#define N_NODES 40000
#define N_EDGES 640000
#define EMBED   128
#define NTYPE   64

// ---------------- scratch (static device globals; no allocs allowed) ----------------
__device__ __half         g_t[N_NODES * EMBED];    // post-GEMM features, fp16
__device__ unsigned short g_hb[N_NODES * EMBED];   // bf16 bits, high part
__device__ unsigned short g_hl[N_NODES * EMBED];   // bf16 bits, low part
__device__ int   g_counts[N_NODES];
__device__ int   g_rowptr[N_NODES + 1];
__device__ int   g_cursor[N_NODES];
__device__ float g_dinv[N_NODES];
__device__ float g_selfw[N_NODES];
__device__ int2  g_edges[N_EDGES];
__device__ int   g_x64;
__device__ int   g_e64;
// weights as bf16 hi/lo, layout [n][k] (k contiguous)
__device__ unsigned short g_Wch[128 * 128];
__device__ unsigned short g_Wcl[128 * 128];
__device__ unsigned short g_Wdh[64 * 128];
__device__ unsigned short g_Wdl[64 * 128];

// ---------------- helpers ----------------
__device__ __forceinline__ int load_idx(const void* p, long long i, int is64) {
    if (is64) return (int)((const long long*)p)[i];
    return ((const int*)p)[i];
}

__device__ __forceinline__ unsigned short f2bf(float x) {
    return __bfloat16_as_ushort(__float2bfloat16_rn(x));
}
__device__ __forceinline__ float bf2f(unsigned short u) {
    return __bfloat162float(__ushort_as_bfloat16(u));
}

__device__ __forceinline__ unsigned int smem_u32(const void* p) {
    unsigned int a;
    asm("{ .reg .u64 t; cvta.to.shared.u64 t, %1; cvt.u32.u64 %0, t; }" : "=r"(a) : "l"(p));
    return a;
}

__device__ __forceinline__ void ldsm_x4(unsigned int& r0, unsigned int& r1,
                                        unsigned int& r2, unsigned int& r3,
                                        unsigned int addr) {
    asm volatile("ldmatrix.sync.aligned.m8n8.x4.shared.b16 {%0,%1,%2,%3}, [%4];"
                 : "=r"(r0), "=r"(r1), "=r"(r2), "=r"(r3) : "r"(addr));
}

__device__ __forceinline__ void ldsm_x2(unsigned int& r0, unsigned int& r1,
                                        unsigned int addr) {
    asm volatile("ldmatrix.sync.aligned.m8n8.x2.shared.b16 {%0,%1}, [%2];"
                 : "=r"(r0), "=r"(r1) : "r"(addr));
}

__device__ __forceinline__ void mma_bf16(float* d, unsigned int a0, unsigned int a1,
                                         unsigned int a2, unsigned int a3,
                                         unsigned int b0, unsigned int b1) {
    asm volatile(
        "mma.sync.aligned.m16n8k16.row.col.f32.bf16.bf16.f32 "
        "{%0,%1,%2,%3}, {%4,%5,%6,%7}, {%8,%9}, {%0,%1,%2,%3};"
        : "+f"(d[0]), "+f"(d[1]), "+f"(d[2]), "+f"(d[3])
        : "r"(a0), "r"(a1), "r"(a2), "r"(a3), "r"(b0), "r"(b1));
}

// ---------------- dtype detection ----------------
__global__ void k_detect(const void* xp, const void* ep) {
    if (threadIdx.x == 0 && blockIdx.x == 0) {
        const unsigned int* w = (const unsigned int*)xp;
        int is64 = 1;
        for (int i = 0; i < 64; i++) {
            if (w[2 * i + 1] != 0u) { is64 = 0; break; }
        }
        g_x64 = is64;
        const unsigned int* we = (const unsigned int*)ep;
        int e64 = 1;
        for (int i = 0; i < 64; i++) {
            if (we[2 * i + 1] != 0u) { e64 = 0; break; }
        }
        g_e64 = e64;
    }
}

// ---------------- CSR build ----------------
__global__ void k_zero() {
    int i = blockIdx.x * blockDim.x + threadIdx.x;
    if (i < N_NODES) g_counts[i] = 0;
}

__global__ void k_count(const void* ei) {
    int e = blockIdx.x * blockDim.x + threadIdx.x;
    if (e < N_EDGES) {
        int d = load_idx(ei, (long long)N_EDGES + e, g_e64);
        atomicAdd(&g_counts[d], 1);
    }
}

__global__ void k_dinv() {
    int v = blockIdx.x * blockDim.x + threadIdx.x;
    if (v < N_NODES) {
        float deg = (float)(g_counts[v] + 1);
        float dv = rsqrtf(deg);
        g_dinv[v] = dv;
        g_selfw[v] = dv * dv;
    }
}

__global__ void k_scan() {
    __shared__ int partial[1024];
    const int CH = (N_NODES + 1023) / 1024;
    int t = threadIdx.x;
    int base = t * CH;
    int s = 0;
    for (int i = 0; i < CH; i++) {
        if (base + i < N_NODES) s += g_counts[base + i];
    }
    partial[t] = s;
    __syncthreads();
    for (int off = 1; off < 1024; off <<= 1) {
        int xv = (t >= off) ? partial[t - off] : 0;
        __syncthreads();
        partial[t] += xv;
        __syncthreads();
    }
    int run = partial[t] - s;
    for (int i = 0; i < CH; i++) {
        int idx = base + i;
        if (idx < N_NODES) {
            g_rowptr[idx] = run;
            g_cursor[idx] = run;
            run += g_counts[idx];
        }
    }
    if (t == 1023) g_rowptr[N_NODES] = run;
}

__global__ void k_fill(const void* ei) {
    int e = blockIdx.x * blockDim.x + threadIdx.x;
    if (e < N_EDGES) {
        int is64 = g_e64;
        int s = load_idx(ei, e, is64);
        int d = load_idx(ei, (long long)N_EDGES + e, is64);
        int pos = atomicAdd(&g_cursor[d], 1);
        int2 v;
        v.x = s;
        v.y = __float_as_int(g_dinv[s] * g_dinv[d]);
        g_edges[pos] = v;
    }
}

// ---------------- weight prep: bf16 hi/lo, [n][k] layout ----------------
__global__ void k_prepW(const float* __restrict__ Wc, const float* __restrict__ Wd) {
    int i = blockIdx.x * blockDim.x + threadIdx.x;
    if (i < 16384) {
        int n = i >> 7;
        int k = i & 127;
        float v = Wc[k * 128 + n];
        unsigned short h = f2bf(v);
        unsigned short l = f2bf(v - bf2f(h));
        g_Wch[n * 128 + k] = h;
        g_Wcl[n * 128 + k] = l;
    } else if (i < 24576) {
        int j = i - 16384;
        int n = j >> 7;
        int k = j & 127;
        float v = Wd[k * 64 + n];
        unsigned short h = f2bf(v);
        unsigned short l = f2bf(v - bf2f(h));
        g_Wdh[n * 128 + k] = h;
        g_Wdl[n * 128 + k] = l;
    }
}

// ---------------- embedding gather ----------------
__global__ void k_embed(const void* xp, const float* __restrict__ Win) {
    int id = blockIdx.x * blockDim.x + threadIdx.x;
    if (id < N_NODES * 16) {
        int v = id >> 4;
        int k0 = (id & 15) * 8;
        int row = load_idx(xp, v, g_x64);
        const float* src = Win + (long)row * EMBED + k0;
        unsigned short hb[8];
        unsigned short lb[8];
        #pragma unroll
        for (int q = 0; q < 8; q++) {
            float a = src[q];
            unsigned short h = f2bf(a);
            hb[q] = h;
            lb[q] = f2bf(a - bf2f(h));
        }
        *(uint4*)(g_hb + (long)v * EMBED + k0) = *(uint4*)hb;
        *(uint4*)(g_hl + (long)v * EMBED + k0) = *(uint4*)lb;
    }
}

// ---------------- tensor-core GEMM (mma.sync bf16, split hi/lo, 3 passes) ----------
// t[M][NCOL] (fp16) = Ah*Wh + Al*Wh + Ah*Wl, fp32 acc.
// smem: Ah, Al, and one B buffer (Bh first, restaged with Bl) -> occupancy 2.
template <int NCOL>
__device__ __forceinline__ void mma_gemm_body(const unsigned short* __restrict__ Wh,
                                              const unsigned short* __restrict__ Wl,
                                              __half* __restrict__ C) {
    const int PAD = 136;
    const int NT = NCOL / 8;
    extern __shared__ unsigned short sm[];
    unsigned short* Ah = sm;                       // [128][PAD]
    unsigned short* Al = Ah + 128 * PAD;
    unsigned short* Bs = Al + 128 * PAD;           // [NCOL][PAD], Bh then Bl

    int tid = threadIdx.x;
    int wid = tid >> 5;
    int lane = tid & 31;
    int row0 = blockIdx.x * 128;

    for (int i = tid; i < 2048; i += 256) {
        int r = i >> 4;
        int k0 = (i & 15) * 8;
        int gr = row0 + r;
        uint4 vh = make_uint4(0u, 0u, 0u, 0u);
        uint4 vl = make_uint4(0u, 0u, 0u, 0u);
        if (gr < N_NODES) {
            vh = *(const uint4*)(g_hb + (long)gr * EMBED + k0);
            vl = *(const uint4*)(g_hl + (long)gr * EMBED + k0);
        }
        *(uint4*)(Ah + r * PAD + k0) = vh;
        *(uint4*)(Al + r * PAD + k0) = vl;
    }
    for (int i = tid; i < NCOL * 16; i += 256) {
        int r = i >> 4;
        int k0 = (i & 15) * 8;
        *(uint4*)(Bs + r * PAD + k0) = *(const uint4*)(Wh + r * 128 + k0);
    }
    __syncthreads();

    int m0 = wid * 16;
    float acc[NT][4];
    #pragma unroll
    for (int j = 0; j < NT; j++) {
        #pragma unroll
        for (int q = 0; q < 4; q++) acc[j][q] = 0.0f;
    }

    const unsigned int sb = smem_u32(sm);
    unsigned int a_off = (unsigned int)((m0 + (lane & 15)) * PAD + (lane >> 4) * 8) * 2u;
    unsigned int b_off = (unsigned int)(((lane & 15) & 7) * PAD + ((lane & 15) >> 3) * 8) * 2u;
    unsigned int a_h = sb + a_off;
    unsigned int a_l = a_h + (unsigned int)(128 * PAD * 2);
    unsigned int b_b = sb + (unsigned int)(256 * PAD * 2) + b_off;

    // pass 0: Ah*Bh ; pass 1: Al*Bh
    #pragma unroll 1
    for (int pass = 0; pass < 2; pass++) {
        unsigned int abase = (pass == 0) ? a_h : a_l;
        #pragma unroll
        for (int ks = 0; ks < 8; ks++) {
            unsigned int a0, a1, a2, a3;
            ldsm_x4(a0, a1, a2, a3, abase + (unsigned int)(ks * 32));
            #pragma unroll
            for (int j = 0; j < NT; j++) {
                unsigned int b0, b1;
                ldsm_x2(b0, b1, b_b + (unsigned int)(j * 8 * PAD * 2 + ks * 32));
                mma_bf16(acc[j], a0, a1, a2, a3, b0, b1);
            }
        }
    }
    // restage B with Wl
    __syncthreads();
    for (int i = tid; i < NCOL * 16; i += 256) {
        int r = i >> 4;
        int k0 = (i & 15) * 8;
        *(uint4*)(Bs + r * PAD + k0) = *(const uint4*)(Wl + r * 128 + k0);
    }
    __syncthreads();
    // pass 2: Ah*Bl
    #pragma unroll
    for (int ks = 0; ks < 8; ks++) {
        unsigned int a0, a1, a2, a3;
        ldsm_x4(a0, a1, a2, a3, a_h + (unsigned int)(ks * 32));
        #pragma unroll
        for (int j = 0; j < NT; j++) {
            unsigned int b0, b1;
            ldsm_x2(b0, b1, b_b + (unsigned int)(j * 8 * PAD * 2 + ks * 32));
            mma_bf16(acc[j], a0, a1, a2, a3, b0, b1);
        }
    }

    // epilogue: fp16 stores
    int mrow = m0 + (lane >> 2);
    int nc0 = (lane & 3) * 2;
    int gr0 = row0 + mrow;
    int gr1 = gr0 + 8;
    #pragma unroll
    for (int j = 0; j < NT; j++) {
        if (gr0 < N_NODES) {
            *(__half2*)(C + (long)gr0 * NCOL + j * 8 + nc0) =
                __floats2half2_rn(acc[j][0], acc[j][1]);
        }
        if (gr1 < N_NODES) {
            *(__half2*)(C + (long)gr1 * NCOL + j * 8 + nc0) =
                __floats2half2_rn(acc[j][2], acc[j][3]);
        }
    }
}

__global__ void __launch_bounds__(256, 2) k_mm_conv() {
    mma_gemm_body<128>(g_Wch, g_Wcl, g_t);
}
__global__ void __launch_bounds__(256, 2) k_mm_dec() {
    mma_gemm_body<64>(g_Wdh, g_Wdl, g_t);
}

// ---------------- aggregation (fp16 gathers, fp32 accumulate) ----------------
// out[v] = postproc( selfw[v]*t[v] + sum_{(u->v)} norm*t[u] + bias )
__global__ void __launch_bounds__(256) k_agg_conv(const float* __restrict__ bias) {
    const __half* T = g_t;
    int v = blockIdx.x * 8 + (threadIdx.x >> 5);
    int lane = threadIdx.x & 31;

    float acc[4];
    float sw = g_selfw[v];
    {
        uint2 raw = *(const uint2*)(T + (long)v * 128 + lane * 4);
        float2 p0 = __half22float2(*(__half2*)&raw.x);
        float2 p1 = __half22float2(*(__half2*)&raw.y);
        acc[0] = sw * p0.x; acc[1] = sw * p0.y;
        acc[2] = sw * p1.x; acc[3] = sw * p1.y;
    }

    int jb = g_rowptr[v];
    int je = g_rowptr[v + 1];
    int j = jb;
    for (; j + 1 < je; j += 2) {
        int2 e0 = g_edges[j];
        int2 e1 = g_edges[j + 1];
        uint2 r0 = *(const uint2*)(T + (long)e0.x * 128 + lane * 4);
        uint2 r1 = *(const uint2*)(T + (long)e1.x * 128 + lane * 4);
        float w0 = __int_as_float(e0.y);
        float w1 = __int_as_float(e1.y);
        float2 a0 = __half22float2(*(__half2*)&r0.x);
        float2 a1 = __half22float2(*(__half2*)&r0.y);
        float2 b0 = __half22float2(*(__half2*)&r1.x);
        float2 b1 = __half22float2(*(__half2*)&r1.y);
        acc[0] = fmaf(w0, a0.x, acc[0]); acc[1] = fmaf(w0, a0.y, acc[1]);
        acc[2] = fmaf(w0, a1.x, acc[2]); acc[3] = fmaf(w0, a1.y, acc[3]);
        acc[0] = fmaf(w1, b0.x, acc[0]); acc[1] = fmaf(w1, b0.y, acc[1]);
        acc[2] = fmaf(w1, b1.x, acc[2]); acc[3] = fmaf(w1, b1.y, acc[3]);
    }
    if (j < je) {
        int2 e0 = g_edges[j];
        uint2 r0 = *(const uint2*)(T + (long)e0.x * 128 + lane * 4);
        float w0 = __int_as_float(e0.y);
        float2 a0 = __half22float2(*(__half2*)&r0.x);
        float2 a1 = __half22float2(*(__half2*)&r0.y);
        acc[0] = fmaf(w0, a0.x, acc[0]); acc[1] = fmaf(w0, a0.y, acc[1]);
        acc[2] = fmaf(w0, a1.x, acc[2]); acc[3] = fmaf(w0, a1.y, acc[3]);
    }

    unsigned short hb[4];
    unsigned short lb[4];
    #pragma unroll
    for (int i = 0; i < 4; i++) {
        float a = fmaxf(acc[i] + bias[lane * 4 + i], 0.0f);
        unsigned short h = f2bf(a);
        hb[i] = h;
        lb[i] = f2bf(a - bf2f(h));
    }
    *(uint2*)(g_hb + (long)v * 128 + lane * 4) = *(uint2*)hb;
    *(uint2*)(g_hl + (long)v * 128 + lane * 4) = *(uint2*)lb;
}

__global__ void __launch_bounds__(256) k_agg_dec(const float* __restrict__ bias,
                                                 float* __restrict__ out) {
    const __half* T = g_t;
    int v = blockIdx.x * 8 + (threadIdx.x >> 5);
    int lane = threadIdx.x & 31;

    float acc[2];
    float sw = g_selfw[v];
    {
        unsigned int raw = *(const unsigned int*)(T + (long)v * 64 + lane * 2);
        float2 p0 = __half22float2(*(__half2*)&raw);
        acc[0] = sw * p0.x; acc[1] = sw * p0.y;
    }

    int jb = g_rowptr[v];
    int je = g_rowptr[v + 1];
    int j = jb;
    for (; j + 1 < je; j += 2) {
        int2 e0 = g_edges[j];
        int2 e1 = g_edges[j + 1];
        unsigned int r0 = *(const unsigned int*)(T + (long)e0.x * 64 + lane * 2);
        unsigned int r1 = *(const unsigned int*)(T + (long)e1.x * 64 + lane * 2);
        float w0 = __int_as_float(e0.y);
        float w1 = __int_as_float(e1.y);
        float2 a0 = __half22float2(*(__half2*)&r0);
        float2 b0 = __half22float2(*(__half2*)&r1);
        acc[0] = fmaf(w0, a0.x, acc[0]); acc[1] = fmaf(w0, a0.y, acc[1]);
        acc[0] = fmaf(w1, b0.x, acc[0]); acc[1] = fmaf(w1, b0.y, acc[1]);
    }
    if (j < je) {
        int2 e0 = g_edges[j];
        unsigned int r0 = *(const unsigned int*)(T + (long)e0.x * 64 + lane * 2);
        float w0 = __int_as_float(e0.y);
        float2 a0 = __half22float2(*(__half2*)&r0);
        acc[0] = fmaf(w0, a0.x, acc[0]); acc[1] = fmaf(w0, a0.y, acc[1]);
    }

    float2 o;
    o.x = acc[0] + bias[lane * 2];
    o.y = acc[1] + bias[lane * 2 + 1];
    *(float2*)(out + (long)v * 64 + lane * 2) = o;
}

// ---------------- launch ----------------
extern "C" void kernel_launch(void* const* d_in, const int* in_sizes, int n_in,
                              void* d_out, int out_size) {
    const void*  x      = d_in[0];
    const void*  ei     = d_in[1];
    const float* W_in   = (const float*)d_in[2];
    const float* W_conv = (const float*)d_in[3];
    const float* b_conv = (const float*)d_in[4];
    const float* W_dec  = (const float*)d_in[5];
    const float* b_dec  = (const float*)d_in[6];
    float* out = (float*)d_out;

    const int PAD = 136;
    const int SMEM_CONV = (2 * 128 + 128) * PAD * 2;  // 104448
    const int SMEM_DEC  = (2 * 128 + 64) * PAD * 2;   //  87040
    cudaFuncSetAttribute(k_mm_conv, cudaFuncAttributeMaxDynamicSharedMemorySize, SMEM_CONV);
    cudaFuncSetAttribute(k_mm_dec,  cudaFuncAttributeMaxDynamicSharedMemorySize, SMEM_DEC);

    k_detect<<<1, 32>>>(x, ei);
    k_zero<<<(N_NODES + 255) / 256, 256>>>();
    k_count<<<(N_EDGES + 255) / 256, 256>>>(ei);
    k_dinv<<<(N_NODES + 255) / 256, 256>>>();
    k_scan<<<1, 1024>>>();
    k_fill<<<(N_EDGES + 255) / 256, 256>>>(ei);
    k_prepW<<<96, 256>>>(W_conv, W_dec);
    k_embed<<<(N_NODES * 16 + 255) / 256, 256>>>(x, W_in);

    const int GEMM_BLOCKS = (N_NODES + 127) / 128;   // 313
    for (int it = 0; it < 4; it++) {
        k_mm_conv<<<GEMM_BLOCKS, 256, SMEM_CONV>>>();
        k_agg_conv<<<5000, 256>>>(b_conv);
    }
    k_mm_dec<<<GEMM_BLOCKS, 256, SMEM_DEC>>>();
    k_agg_dec<<<5000, 256>>>(b_dec, out);
}